// round 6
// baseline (speedup 1.0000x reference)
#include <cuda_runtime.h>

#define BASIS 1e-10f
#define TPB   128
#define CHUNK 4
#define SPAN  (TPB * CHUNK)   // 512 tiles per block

__device__ __forceinline__ float ex2_approx(float x) {
    float y; asm("ex2.approx.ftz.f32 %0, %1;" : "=f"(y) : "f"(x)); return y;
}
__device__ __forceinline__ float rcp_approx(float x) {
    float y; asm("rcp.approx.ftz.f32 %0, %1;" : "=f"(y) : "f"(x)); return y;
}

__global__ void __launch_bounds__(TPB) transition_prob_fused(
    const float* __restrict__ adstock,
    const float* __restrict__ mu,
    const float* __restrict__ beta,
    const float* __restrict__ init_prob,
    const float* __restrict__ click_prob,
    float* __restrict__ out,
    int days, int dur, int total9)
{
    __shared__ float s[SPAN * 9];
    const int tid      = threadIdx.x;
    const int row      = blockIdx.y;
    const int tileBase = blockIdx.x * SPAN;

    // Broadcast loads of the 12 params (uniform addr -> 1 wavefront, L1 hit),
    // pre-scaled by log2(e) so exp(x) = ex2(x') with constants folded into FMA.
    const float L2E = 1.4426950408889634f;
    float bb[9], mm[3];
    #pragma unroll
    for (int i = 0; i < 9; i++) bb[i] = __ldg(beta + i) * L2E;
    #pragma unroll
    for (int i = 0; i < 3; i++) mm[i] = __ldg(mu + i) * L2E;

    // 32-bit indexing throughout (max element offset ~38M)
    const int aBase = row * 3 * days + tileBase + tid + 1;
    const float* ap0 = adstock + aBase;
    const float* ap1 = ap0 + days;
    const float* ap2 = ap1 + days;
    const int d0 = tileBase + tid;

    #pragma unroll
    for (int j = 0; j < CHUNK; j++) {
        const int d = d0 + j * TPB;          // strided tile assignment
        if (d < dur) {
            const float a0 = __ldcs(ap0 + j * TPB);
            const float a1 = __ldcs(ap1 + j * TPB);
            const float a2 = __ldcs(ap2 + j * TPB);

            const float t1 = fmaf(a0, bb[0], fmaf(a1, bb[3], fmaf(a2, bb[6], mm[0])));
            const float t2 = fmaf(a0, bb[1], fmaf(a1, bb[4], fmaf(a2, bb[7], mm[1])));
            const float t3 = fmaf(a0, bb[2], fmaf(a1, bb[5], fmaf(a2, bb[8], mm[2])));

            const float n01 = ex2_approx(t1);
            const float n10 = ex2_approx(t2);
            const float n11 = ex2_approx(t3);

            const float id0 = rcp_approx(1.0f + n01);
            const float id1 = rcp_approx(1.0f + n10 + n11);

            // stride-9 floats across lanes: 9 coprime 32 -> conflict-free STS
            float* sp = s + (tid + j * TPB) * 9;
            sp[0] = fmaxf(id0,       BASIS);
            sp[1] = fmaxf(n01 * id0, BASIS);
            sp[2] = BASIS;
            sp[3] = fmaxf(n10 * id1, BASIS);
            sp[4] = fmaxf(id1,       BASIS);
            sp[5] = fmaxf(n11 * id1, BASIS);
            sp[6] = BASIS;
            sp[7] = BASIS;
            sp[8] = 1.0f;
        }
    }
    __syncthreads();

    int nTiles = dur - tileBase;
    if (nTiles > SPAN) nTiles = SPAN;
    const int outOff = (row * dur + tileBase) * 9;
    float* ob = out + outOff;

    if (nTiles == SPAN && (outOff & 3) == 0) {
        // static, fully unrolled coalesced copy-out: 1152 float4 = 9 per thread
        const float4* s4 = (const float4*)s;
        float4* o4 = (float4*)ob;
        #pragma unroll
        for (int j = 0; j < 9; j++)
            __stcs(o4 + tid + j * TPB, s4[tid + j * TPB]);
    } else {
        const int nFloats = nTiles * 9;
        for (int i = tid; i < nFloats; i += TPB)
            __stcs(ob + i, s[i]);
    }

    if ((row | blockIdx.x | tid) == 0) {
        out[total9]     = 1.0f / (1.0f + __expf(-__ldg(init_prob)));
        out[total9 + 1] = 1.0f / (1.0f + __expf(-__ldg(click_prob)));
    }
}

extern "C" void kernel_launch(void* const* d_in, const int* in_sizes, int n_in,
                              void* d_out, int out_size)
{
    const float* adstock    = (const float*)d_in[0];
    const float* mu         = (const float*)d_in[1];
    const float* beta       = (const float*)d_in[2];
    const float* init_prob  = (const float*)d_in[3];
    const float* click_prob = (const float*)d_in[4];
    float* out = (float*)d_out;

    const long long in0 = (long long)in_sizes[0];        // b * 3 * days
    const long long q   = ((long long)out_size - 2) / 9; // b * (days-1)
    const long long bd  = in0 / 3;                       // b * days
    const long long b   = bd - q;                        // b
    const int days      = (int)(bd / b);
    const int dur       = days - 1;

    dim3 grid((unsigned)((dur + SPAN - 1) / SPAN), (unsigned)b);
    transition_prob_fused<<<grid, TPB>>>(adstock, mu, beta, init_prob, click_prob,
                                         out, days, dur, (int)(q * 9));
}

// round 7
// speedup vs baseline: 1.0583x; 1.0583x over previous
#include <cuda_runtime.h>

#define BASIS 1e-10f
#define TPB   128
#define CHUNK 4
#define SPAN  (TPB * CHUNK)   // 512 tiles per block

__device__ __forceinline__ float ex2_approx(float x) {
    float y; asm("ex2.approx.ftz.f32 %0, %1;" : "=f"(y) : "f"(x)); return y;
}
__device__ __forceinline__ float rcp_approx(float x) {
    float y; asm("rcp.approx.ftz.f32 %0, %1;" : "=f"(y) : "f"(x)); return y;
}

__global__ void __launch_bounds__(TPB) transition_prob_fused(
    const float* __restrict__ adstock,
    const float* __restrict__ mu,
    const float* __restrict__ beta,
    const float* __restrict__ init_prob,
    const float* __restrict__ click_prob,
    float* __restrict__ out,
    int days, int dur, int total9)
{
    __shared__ float s[SPAN * 9];
    const int tid      = threadIdx.x;
    const int row      = blockIdx.y;
    const int tileBase = blockIdx.x * SPAN;

    // Broadcast loads of the 12 params (uniform addr -> 1 wavefront, L1 hit),
    // pre-scaled by log2(e) so exp(x) = ex2(x') with constants folded into FMA.
    const float L2E = 1.4426950408889634f;
    float bb[9], mm[3];
    #pragma unroll
    for (int i = 0; i < 9; i++) bb[i] = __ldg(beta + i) * L2E;
    #pragma unroll
    for (int i = 0; i < 3; i++) mm[i] = __ldg(mu + i) * L2E;

    // 32-bit indexing throughout (max element offset ~38M)
    const float* ap = adstock + row * 3 * days + 1;
    const int d0 = tileBase + tid;

    // ---- Front-batched loads: clamp instead of branch so all 12 loads issue
    // unconditionally (MLP=12). Clamped lanes produce garbage that is only
    // written to smem slots the guarded copy-out never reads.
    float a0[CHUNK], a1[CHUNK], a2[CHUNK];
    #pragma unroll
    for (int j = 0; j < CHUNK; j++) {
        int d = d0 + j * TPB;
        d = (d < dur) ? d : (dur - 1);
        a0[j] = __ldcs(ap + d);
        a1[j] = __ldcs(ap + d + days);
        a2[j] = __ldcs(ap + d + 2 * days);
    }

    #pragma unroll
    for (int j = 0; j < CHUNK; j++) {
        const float t1 = fmaf(a0[j], bb[0], fmaf(a1[j], bb[3], fmaf(a2[j], bb[6], mm[0])));
        const float t2 = fmaf(a0[j], bb[1], fmaf(a1[j], bb[4], fmaf(a2[j], bb[7], mm[1])));
        const float t3 = fmaf(a0[j], bb[2], fmaf(a1[j], bb[5], fmaf(a2[j], bb[8], mm[2])));

        const float n01 = ex2_approx(t1);
        const float n10 = ex2_approx(t2);
        const float n11 = ex2_approx(t3);

        const float id0 = rcp_approx(1.0f + n01);
        const float id1 = rcp_approx(1.0f + n10 + n11);

        // stride-9 floats across lanes: 9 coprime 32 -> conflict-free STS
        float* sp = s + (tid + j * TPB) * 9;
        sp[0] = fmaxf(id0,       BASIS);
        sp[1] = fmaxf(n01 * id0, BASIS);
        sp[2] = BASIS;
        sp[3] = fmaxf(n10 * id1, BASIS);
        sp[4] = fmaxf(id1,       BASIS);
        sp[5] = fmaxf(n11 * id1, BASIS);
        sp[6] = BASIS;
        sp[7] = BASIS;
        sp[8] = 1.0f;
    }
    __syncthreads();

    int nTiles = dur - tileBase;
    if (nTiles > SPAN) nTiles = SPAN;
    const int outOff = (row * dur + tileBase) * 9;
    float* ob = out + outOff;

    if (nTiles == SPAN && (outOff & 3) == 0) {
        // static, fully unrolled coalesced copy-out: 1152 float4 = 9 per thread
        const float4* s4 = (const float4*)s;
        float4* o4 = (float4*)ob;
        #pragma unroll
        for (int j = 0; j < 9; j++)
            __stcs(o4 + tid + j * TPB, s4[tid + j * TPB]);
    } else {
        const int nFloats = nTiles * 9;
        for (int i = tid; i < nFloats; i += TPB)
            __stcs(ob + i, s[i]);
    }

    if ((row | blockIdx.x | tid) == 0) {
        out[total9]     = 1.0f / (1.0f + __expf(-__ldg(init_prob)));
        out[total9 + 1] = 1.0f / (1.0f + __expf(-__ldg(click_prob)));
    }
}

extern "C" void kernel_launch(void* const* d_in, const int* in_sizes, int n_in,
                              void* d_out, int out_size)
{
    const float* adstock    = (const float*)d_in[0];
    const float* mu         = (const float*)d_in[1];
    const float* beta       = (const float*)d_in[2];
    const float* init_prob  = (const float*)d_in[3];
    const float* click_prob = (const float*)d_in[4];
    float* out = (float*)d_out;

    const long long in0 = (long long)in_sizes[0];        // b * 3 * days
    const long long q   = ((long long)out_size - 2) / 9; // b * (days-1)
    const long long bd  = in0 / 3;                       // b * days
    const long long b   = bd - q;                        // b
    const int days      = (int)(bd / b);
    const int dur       = days - 1;

    dim3 grid((unsigned)((dur + SPAN - 1) / SPAN), (unsigned)b);
    transition_prob_fused<<<grid, TPB>>>(adstock, mu, beta, init_prob, click_prob,
                                         out, days, dur, (int)(q * 9));
}

// round 8
// speedup vs baseline: 1.1667x; 1.1024x over previous
#include <cuda_runtime.h>

#define BASIS 1e-10f
#define TPB   128
#define WARP_TILES 128                 // tiles per warp (9*128/4 = 288 float4 = 9/lane)
#define SPAN  (4 * WARP_TILES)         // 512 tiles per block (TPB/32 warps)

__device__ __forceinline__ float ex2_approx(float x) {
    float y; asm("ex2.approx.ftz.f32 %0, %1;" : "=f"(y) : "f"(x)); return y;
}
__device__ __forceinline__ float rcp_approx(float x) {
    float y; asm("rcp.approx.ftz.f32 %0, %1;" : "=f"(y) : "f"(x)); return y;
}

__global__ void __launch_bounds__(TPB) transition_prob_fused(
    const float* __restrict__ adstock,
    const float* __restrict__ mu,
    const float* __restrict__ beta,
    const float* __restrict__ init_prob,
    const float* __restrict__ click_prob,
    float* __restrict__ out,
    int days, int dur, int total9)
{
    __shared__ float s[SPAN * 9];
    const int tid      = threadIdx.x;
    const int w        = tid >> 5;          // warp id in block
    const int l        = tid & 31;          // lane
    const int row      = blockIdx.y;
    const int tileBase = blockIdx.x * SPAN;
    const int warpTile = tileBase + (w << 7);   // this warp's first tile

    // Broadcast loads of the 12 params (uniform addr -> 1 wavefront, L1 hit),
    // pre-scaled by log2(e) so exp(x) = ex2(x') with constants folded into FMA.
    const float L2E = 1.4426950408889634f;
    float bb[9], mm[3];
    #pragma unroll
    for (int i = 0; i < 9; i++) bb[i] = __ldg(beta + i) * L2E;
    #pragma unroll
    for (int i = 0; i < 3; i++) mm[i] = __ldg(mu + i) * L2E;

    // 32-bit indexing throughout (max element offset ~38M)
    const float* ap = adstock + row * 3 * days + 1;
    float* sw = s + (w << 7) * 9;           // warp-private smem slice (4608 B)

    // ---- Front-batched loads, clamped (no branch) so all 12 issue up front.
    float a0[4], a1[4], a2[4];
    #pragma unroll
    for (int k = 0; k < 4; k++) {
        int d = warpTile + l + (k << 5);
        d = (d < dur) ? d : (dur - 1);
        a0[k] = __ldcs(ap + d);
        a1[k] = __ldcs(ap + d + days);
        a2[k] = __ldcs(ap + d + 2 * days);
    }

    #pragma unroll
    for (int k = 0; k < 4; k++) {
        const float t1 = fmaf(a0[k], bb[0], fmaf(a1[k], bb[3], fmaf(a2[k], bb[6], mm[0])));
        const float t2 = fmaf(a0[k], bb[1], fmaf(a1[k], bb[4], fmaf(a2[k], bb[7], mm[1])));
        const float t3 = fmaf(a0[k], bb[2], fmaf(a1[k], bb[5], fmaf(a2[k], bb[8], mm[2])));

        const float n01 = ex2_approx(t1);
        const float n10 = ex2_approx(t2);
        const float n11 = ex2_approx(t3);

        const float id0 = rcp_approx(1.0f + n01);
        const float id1 = rcp_approx(1.0f + n10 + n11);

        // stride-9 floats across lanes: 9 coprime 32 -> conflict-free STS
        float* sp = sw + (l + (k << 5)) * 9;
        sp[0] = fmaxf(id0,       BASIS);
        sp[1] = fmaxf(n01 * id0, BASIS);
        sp[2] = BASIS;
        sp[3] = fmaxf(n10 * id1, BASIS);
        sp[4] = fmaxf(id1,       BASIS);
        sp[5] = fmaxf(n11 * id1, BASIS);
        sp[6] = BASIS;
        sp[7] = BASIS;
        sp[8] = 1.0f;
    }
    __syncwarp();   // warp-autonomous: no block barrier anywhere

    // ---- Warp-private coalesced copy-out: 288 float4 = 9 per lane
    const int warpOutOff = (row * dur + warpTile) * 9;
    if (warpTile + WARP_TILES <= dur && (warpOutOff & 3) == 0) {
        const float4* s4 = (const float4*)sw;
        float4* o4 = (float4*)(out + warpOutOff);
        #pragma unroll
        for (int j = 0; j < 9; j++)
            __stcs(o4 + l + (j << 5), s4[l + (j << 5)]);
    } else if (warpTile < dur) {
        const int nFloats = (dur - warpTile) * 9;
        for (int i = l; i < nFloats; i += 32)
            __stcs(out + warpOutOff + i, sw[i]);
    }

    if ((row | blockIdx.x | tid) == 0) {
        out[total9]     = 1.0f / (1.0f + __expf(-__ldg(init_prob)));
        out[total9 + 1] = 1.0f / (1.0f + __expf(-__ldg(click_prob)));
    }
}

extern "C" void kernel_launch(void* const* d_in, const int* in_sizes, int n_in,
                              void* d_out, int out_size)
{
    const float* adstock    = (const float*)d_in[0];
    const float* mu         = (const float*)d_in[1];
    const float* beta       = (const float*)d_in[2];
    const float* init_prob  = (const float*)d_in[3];
    const float* click_prob = (const float*)d_in[4];
    float* out = (float*)d_out;

    const long long in0 = (long long)in_sizes[0];        // b * 3 * days
    const long long q   = ((long long)out_size - 2) / 9; // b * (days-1)
    const long long bd  = in0 / 3;                       // b * days
    const long long b   = bd - q;                        // b
    const int days      = (int)(bd / b);
    const int dur       = days - 1;

    dim3 grid((unsigned)((dur + SPAN - 1) / SPAN), (unsigned)b);
    transition_prob_fused<<<grid, TPB>>>(adstock, mu, beta, init_prob, click_prob,
                                         out, days, dur, (int)(q * 9));
}